// round 1
// baseline (speedup 1.0000x reference)
#include <cuda_runtime.h>
#include <cuda_bf16.h>
#include <cstdint>

// Problem constants
#define BB 2
#define SS 2048
#define DD 1024
#define HH 16
#define HKK 4
#define HDD 64
#define WINN 1024
#define EE 8
#define TOPK 2
#define DHH 2048
#define ROWS (BB*SS)          // 4096
#define NASSIGN (ROWS*TOPK)   // 8192

// ---------------- scratch (static device globals; no allocations) ----------------
__device__ float g_hn[ROWS*DD];
__device__ float g_q [ROWS*HH*HDD];
__device__ float g_k [ROWS*HKK*HDD];
__device__ float g_v [ROWS*HKK*HDD];
__device__ float g_o [ROWS*HH*HDD];
__device__ float g_h [ROWS*DD];
__device__ float g_fn[ROWS*DD];
__device__ float g_h1[NASSIGN*DHH];   // 64 MB
__device__ float g_r [NASSIGN*DD];    // 32 MB
__device__ int   g_counts[EE];
__device__ int   g_cursor[EE];
__device__ int   g_offsets[EE+1];
__device__ int   g_topi[NASSIGN];
__device__ float g_topg[NASSIGN];
__device__ int   g_arow[NASSIGN];
__device__ float g_agate[NASSIGN];
__device__ int   g_adst[NASSIGN];

// ---------------- small kernels ----------------
__global__ void zero_kernel() {
    int t = threadIdx.x;
    if (t < EE) { g_counts[t] = 0; g_cursor[t] = 0; }
}

__global__ void rmsnorm_kernel(const float* __restrict__ x, const float* __restrict__ w,
                               float* __restrict__ y, float eps) {
    int row = blockIdx.x;
    int tid = threadIdx.x;                 // 256
    const float* xr = x + (size_t)row * DD;
    float s = 0.f;
    for (int d = tid; d < DD; d += 256) { float v = xr[d]; s += v * v; }
    __shared__ float red[256];
    red[tid] = s; __syncthreads();
    for (int st = 128; st > 0; st >>= 1) {
        if (tid < st) red[tid] += red[tid + st];
        __syncthreads();
    }
    float rms = rsqrtf(red[0] / (float)DD + eps);
    float* yr = y + (size_t)row * DD;
    for (int d = tid; d < DD; d += 256) yr[d] = xr[d] * rms * w[d];
}

__global__ void rope_kernel(float* __restrict__ t, const float* __restrict__ fc,
                            const float* __restrict__ fs, int nh, int total) {
    int idx = blockIdx.x * blockDim.x + threadIdx.x;
    if (idx >= total) return;              // total = ROWS*nh*32
    int i = idx & 31;
    int h = (idx >> 5) % nh;
    int r = idx / (nh * 32);               // b*S + s
    int s = r & (SS - 1);
    float c  = fc[s * 32 + i];
    float sn = fs[s * 32 + i];
    size_t base = (size_t)r * (nh * HDD) + h * HDD + 2 * i;
    float t0 = t[base], t1 = t[base + 1];
    t[base]     = t0 * c - t1 * sn;
    t[base + 1] = t0 * sn + t1 * c;
}

// ---------------- generic tiled SGEMM: C = A(MxK) @ B(KxN) [+X] ----------------
// grid: (N/64, M/64), block 256. M,N multiples of 64; K multiple of 16.
__global__ void sgemm_kernel(const float* __restrict__ A, const float* __restrict__ B,
                             const float* __restrict__ X, float* __restrict__ C,
                             int M, int N, int K) {
    __shared__ __align__(16) float As[16][64];
    __shared__ __align__(16) float Bs[16][64];
    const int tid = threadIdx.x, tx = tid & 15, ty = tid >> 4;
    const int row0 = blockIdx.y * 64, col0 = blockIdx.x * 64;
    float acc[4][4] = {};
    for (int kk = 0; kk < K; kk += 16) {
        #pragma unroll
        for (int i = 0; i < 4; i++) {
            int idx = tid + i * 256; int r = idx >> 4, c = idx & 15;
            As[c][r] = A[(size_t)(row0 + r) * K + kk + c];
        }
        #pragma unroll
        for (int i = 0; i < 4; i++) {
            int idx = tid + i * 256; int r = idx >> 6, c = idx & 63;
            Bs[r][c] = B[(size_t)(kk + r) * N + col0 + c];
        }
        __syncthreads();
        #pragma unroll
        for (int k = 0; k < 16; k++) {
            float4 a = *reinterpret_cast<const float4*>(&As[k][ty * 4]);
            float4 b = *reinterpret_cast<const float4*>(&Bs[k][tx * 4]);
            acc[0][0] += a.x*b.x; acc[0][1] += a.x*b.y; acc[0][2] += a.x*b.z; acc[0][3] += a.x*b.w;
            acc[1][0] += a.y*b.x; acc[1][1] += a.y*b.y; acc[1][2] += a.y*b.z; acc[1][3] += a.y*b.w;
            acc[2][0] += a.z*b.x; acc[2][1] += a.z*b.y; acc[2][2] += a.z*b.z; acc[2][3] += a.z*b.w;
            acc[3][0] += a.w*b.x; acc[3][1] += a.w*b.y; acc[3][2] += a.w*b.z; acc[3][3] += a.w*b.w;
        }
        __syncthreads();
    }
    #pragma unroll
    for (int i = 0; i < 4; i++) {
        size_t base = (size_t)(row0 + ty * 4 + i) * N + col0 + tx * 4;
        #pragma unroll
        for (int j = 0; j < 4; j++) {
            float v = acc[i][j];
            if (X) v += X[base + j];
            C[base + j] = v;
        }
    }
}

// ---------------- flash attention: 64-query x 32-key tiles ----------------
// grid (S/64, H, B), block 256
__global__ void attn_kernel(const float* __restrict__ q, const float* __restrict__ kmat,
                            const float* __restrict__ vmat, float* __restrict__ o) {
    const int qt = blockIdx.x, h = blockIdx.y, b = blockIdx.z;
    const int hk = h >> 2;                       // H/HK = 4
    const int q0 = qt * 64;
    __shared__ __align__(16) float Qs[64][68];   // [d][qr]
    __shared__ __align__(16) float Ks[64][36];   // [d][jc]
    __shared__ __align__(16) float Vs[32][68];   // [j][d]
    __shared__ __align__(16) float Ps[64][36];   // scores -> probs
    __shared__ float m_s[64], l_s[64], al_s[64];
    const int tid = threadIdx.x;
    const int tx = tid & 15, ty = tid >> 4;

    #pragma unroll
    for (int i = 0; i < 16; i++) {
        int idx = tid + i * 256; int d = idx & 63, r = idx >> 6;
        Qs[d][r] = q[((size_t)(b * SS + q0 + r)) * (HH*HDD) + h * HDD + d];
    }
    if (tid < 64) { m_s[tid] = -1e30f; l_s[tid] = 0.f; }
    __syncthreads();

    float acc[4][4] = {};
    int jlo = q0 - (WINN - 1); if (jlo < 0) jlo = 0;
    const int jt0 = jlo >> 5, jt1 = (q0 + 63) >> 5;
    for (int jt = jt0; jt <= jt1; jt++) {
        const int j0 = jt << 5;
        #pragma unroll
        for (int i = 0; i < 8; i++) {            // K tile: 64d x 32j
            int idx = tid + i * 256; int d = idx & 63, r = idx >> 6;
            Ks[d][r] = kmat[((size_t)(b * SS + j0 + r)) * (HKK*HDD) + hk * HDD + d];
        }
        __syncthreads();
        float s2[4][2] = {};
        #pragma unroll
        for (int d = 0; d < 64; d++) {
            float4 a  = *reinterpret_cast<const float4*>(&Qs[d][ty * 4]);
            float2 bq = *reinterpret_cast<const float2*>(&Ks[d][tx * 2]);
            s2[0][0] += a.x*bq.x; s2[0][1] += a.x*bq.y;
            s2[1][0] += a.y*bq.x; s2[1][1] += a.y*bq.y;
            s2[2][0] += a.z*bq.x; s2[2][1] += a.z*bq.y;
            s2[3][0] += a.w*bq.x; s2[3][1] += a.w*bq.y;
        }
        #pragma unroll
        for (int i2 = 0; i2 < 4; i2++)
            #pragma unroll
            for (int j2 = 0; j2 < 2; j2++) {
                int qi = q0 + ty * 4 + i2, kj = j0 + tx * 2 + j2;
                bool ok = (kj <= qi) && (qi - kj < WINN);
                Ps[ty*4+i2][tx*2+j2] = ok ? s2[i2][j2] * 0.125f : -1e30f;
            }
        __syncthreads();                          // Ks reads done, Ps written
        #pragma unroll
        for (int i = 0; i < 8; i++) {            // V tile (reuses phase)
            int idx = tid + i * 256; int d = idx & 63, r = idx >> 6;
            Vs[r][d] = vmat[((size_t)(b * SS + j0 + r)) * (HKK*HDD) + hk * HDD + d];
        }
        if (tid < 64) {                          // online softmax, row = tid
            float m_old = m_s[tid];
            float mx = m_old;
            #pragma unroll
            for (int c = 0; c < 32; c++) mx = fmaxf(mx, Ps[tid][c]);
            float alpha = __expf(m_old - mx);
            float lsum = 0.f;
            #pragma unroll
            for (int c = 0; c < 32; c++) {
                float s = Ps[tid][c];
                float p = (s < -1e29f) ? 0.f : __expf(s - mx);
                Ps[tid][c] = p; lsum += p;
            }
            l_s[tid] = l_s[tid] * alpha + lsum;
            m_s[tid] = mx; al_s[tid] = alpha;
        }
        __syncthreads();
        #pragma unroll
        for (int i2 = 0; i2 < 4; i2++) {
            float al = al_s[ty * 4 + i2];
            acc[i2][0]*=al; acc[i2][1]*=al; acc[i2][2]*=al; acc[i2][3]*=al;
        }
        #pragma unroll
        for (int c = 0; c < 32; c++) {
            float4 bv = *reinterpret_cast<const float4*>(&Vs[c][tx * 4]);
            #pragma unroll
            for (int i2 = 0; i2 < 4; i2++) {
                float p = Ps[ty*4+i2][c];
                acc[i2][0]+=p*bv.x; acc[i2][1]+=p*bv.y; acc[i2][2]+=p*bv.z; acc[i2][3]+=p*bv.w;
            }
        }
        __syncthreads();
    }
    #pragma unroll
    for (int i2 = 0; i2 < 4; i2++) {
        int qr = ty * 4 + i2;
        float inv = 1.f / l_s[qr];
        size_t base = ((size_t)(b * SS + q0 + qr)) * (HH*HDD) + h * HDD + tx * 4;
        o[base+0]=acc[i2][0]*inv; o[base+1]=acc[i2][1]*inv;
        o[base+2]=acc[i2][2]*inv; o[base+3]=acc[i2][3]*inv;
    }
}

// ---------------- router / MoE ----------------
__global__ void router_kernel(const float* __restrict__ fn, const float* __restrict__ rw) {
    const int row = blockIdx.x;
    const int tid = threadIdx.x;           // 128
    float l[EE] = {};
    for (int d = tid; d < DD; d += 128) {
        float x = fn[(size_t)row * DD + d];
        #pragma unroll
        for (int e = 0; e < EE; e++) l[e] += x * rw[d * EE + e];
    }
    __shared__ float part[EE][128];
    #pragma unroll
    for (int e = 0; e < EE; e++) part[e][tid] = l[e];
    __syncthreads();
    for (int st = 64; st > 0; st >>= 1) {
        if (tid < st) {
            #pragma unroll
            for (int e = 0; e < EE; e++) part[e][tid] += part[e][tid + st];
        }
        __syncthreads();
    }
    if (tid == 0) {
        float lg[EE];
        #pragma unroll
        for (int e = 0; e < EE; e++) lg[e] = part[e][0];
        int i1 = 0;
        #pragma unroll
        for (int e = 1; e < EE; e++) if (lg[e] > lg[i1]) i1 = e;
        int i2 = (i1 == 0) ? 1 : 0;
        #pragma unroll
        for (int e = 0; e < EE; e++) if (e != i1 && lg[e] > lg[i2]) i2 = e;
        float g1 = 1.f / (1.f + __expf(lg[i2] - lg[i1]));
        float g2 = 1.f - g1;
        g_topi[row*2]   = i1; g_topg[row*2]   = g1;
        g_topi[row*2+1] = i2; g_topg[row*2+1] = g2;
        atomicAdd(&g_counts[i1], 1);
        atomicAdd(&g_counts[i2], 1);
    }
}

__global__ void scan_kernel() {
    int s = 0;
    for (int e = 0; e < EE; e++) { g_offsets[e] = s; s += g_counts[e]; }
    g_offsets[EE] = s;
}

__global__ void scatter_kernel() {
    int idx = blockIdx.x * blockDim.x + threadIdx.x;
    if (idx >= NASSIGN) return;
    int e = g_topi[idx];
    int pos = atomicAdd(&g_cursor[e], 1);
    int a = g_offsets[e] + pos;
    g_arow[a]  = idx >> 1;
    g_agate[a] = g_topg[idx];
    g_adst[a]  = idx;
}

// H1 = silu(fn[rows_e] @ w1[e]); grid (DH/64, 64, E)
__global__ void moe_gemm1_kernel(const float* __restrict__ fn, const float* __restrict__ w1) {
    const int e = blockIdx.z;
    const int cnt = g_counts[e];
    const int rt0 = blockIdx.y * 64;
    if (rt0 >= cnt) return;
    const int off = g_offsets[e];
    const float* B = w1 + (size_t)e * DD * DHH;
    __shared__ __align__(16) float As[16][64];
    __shared__ __align__(16) float Bs[16][64];
    __shared__ int rows[64];
    const int tid = threadIdx.x, tx = tid & 15, ty = tid >> 4;
    if (tid < 64) {
        int r = rt0 + tid;
        rows[tid] = g_arow[off + (r < cnt ? r : 0)];
    }
    __syncthreads();
    float acc[4][4] = {};
    const int col0 = blockIdx.x * 64;
    for (int kk = 0; kk < DD; kk += 16) {
        #pragma unroll
        for (int i = 0; i < 4; i++) {
            int idx = tid + i * 256; int r = idx >> 4, c = idx & 15;
            As[c][r] = fn[(size_t)rows[r] * DD + kk + c];
        }
        #pragma unroll
        for (int i = 0; i < 4; i++) {
            int idx = tid + i * 256; int r = idx >> 6, c = idx & 63;
            Bs[r][c] = B[(size_t)(kk + r) * DHH + col0 + c];
        }
        __syncthreads();
        #pragma unroll
        for (int k = 0; k < 16; k++) {
            float4 a = *reinterpret_cast<const float4*>(&As[k][ty * 4]);
            float4 b = *reinterpret_cast<const float4*>(&Bs[k][tx * 4]);
            acc[0][0] += a.x*b.x; acc[0][1] += a.x*b.y; acc[0][2] += a.x*b.z; acc[0][3] += a.x*b.w;
            acc[1][0] += a.y*b.x; acc[1][1] += a.y*b.y; acc[1][2] += a.y*b.z; acc[1][3] += a.y*b.w;
            acc[2][0] += a.z*b.x; acc[2][1] += a.z*b.y; acc[2][2] += a.z*b.z; acc[2][3] += a.z*b.w;
            acc[3][0] += a.w*b.x; acc[3][1] += a.w*b.y; acc[3][2] += a.w*b.z; acc[3][3] += a.w*b.w;
        }
        __syncthreads();
    }
    #pragma unroll
    for (int i = 0; i < 4; i++) {
        int r = rt0 + ty * 4 + i;
        if (r < cnt) {
            size_t base = (size_t)(off + r) * DHH + col0 + tx * 4;
            #pragma unroll
            for (int j = 0; j < 4; j++) {
                float v = acc[i][j];
                g_h1[base + j] = v / (1.f + __expf(-v));     // silu
            }
        }
    }
}

// r[(row,slot)] = gate * (H1 @ w2[e]); grid (D/64, 64, E)
__global__ void moe_gemm2_kernel(const float* __restrict__ w2) {
    const int e = blockIdx.z;
    const int cnt = g_counts[e];
    const int rt0 = blockIdx.y * 64;
    if (rt0 >= cnt) return;
    const int off = g_offsets[e];
    const float* B = w2 + (size_t)e * DHH * DD;
    __shared__ __align__(16) float As[16][64];
    __shared__ __align__(16) float Bs[16][64];
    const int tid = threadIdx.x, tx = tid & 15, ty = tid >> 4;
    float acc[4][4] = {};
    const int col0 = blockIdx.x * 64;
    for (int kk = 0; kk < DHH; kk += 16) {
        #pragma unroll
        for (int i = 0; i < 4; i++) {
            int idx = tid + i * 256; int r = idx >> 4, c = idx & 15;
            int ar = rt0 + r; if (ar >= cnt) ar = cnt - 1;
            As[c][r] = g_h1[(size_t)(off + ar) * DHH + kk + c];
        }
        #pragma unroll
        for (int i = 0; i < 4; i++) {
            int idx = tid + i * 256; int r = idx >> 6, c = idx & 63;
            Bs[r][c] = B[(size_t)(kk + r) * DD + col0 + c];
        }
        __syncthreads();
        #pragma unroll
        for (int k = 0; k < 16; k++) {
            float4 a = *reinterpret_cast<const float4*>(&As[k][ty * 4]);
            float4 b = *reinterpret_cast<const float4*>(&Bs[k][tx * 4]);
            acc[0][0] += a.x*b.x; acc[0][1] += a.x*b.y; acc[0][2] += a.x*b.z; acc[0][3] += a.x*b.w;
            acc[1][0] += a.y*b.x; acc[1][1] += a.y*b.y; acc[1][2] += a.y*b.z; acc[1][3] += a.y*b.w;
            acc[2][0] += a.z*b.x; acc[2][1] += a.z*b.y; acc[2][2] += a.z*b.z; acc[2][3] += a.z*b.w;
            acc[3][0] += a.w*b.x; acc[3][1] += a.w*b.y; acc[3][2] += a.w*b.z; acc[3][3] += a.w*b.w;
        }
        __syncthreads();
    }
    #pragma unroll
    for (int i = 0; i < 4; i++) {
        int r = rt0 + ty * 4 + i;
        if (r < cnt) {
            int dst = g_adst[off + r];
            float gate = g_agate[off + r];
            size_t base = (size_t)dst * DD + col0 + tx * 4;
            #pragma unroll
            for (int j = 0; j < 4; j++) g_r[base + j] = gate * acc[i][j];
        }
    }
}

__global__ void final_add_kernel(float* __restrict__ out) {
    int idx = blockIdx.x * blockDim.x + threadIdx.x;
    if (idx >= ROWS * DD) return;
    int row = idx >> 10, col = idx & 1023;
    out[idx] = g_h[idx] + g_r[((size_t)row * 2) * DD + col]
                        + g_r[((size_t)row * 2 + 1) * DD + col];
}

// ---------------- launch ----------------
extern "C" void kernel_launch(void* const* d_in, const int* in_sizes, int n_in,
                              void* d_out, int out_size) {
    const float* x      = (const float*)d_in[0];
    const float* fcos   = (const float*)d_in[1];
    const float* fsin   = (const float*)d_in[2];
    const float* anw    = (const float*)d_in[3];
    const float* wq     = (const float*)d_in[4];
    const float* wk     = (const float*)d_in[5];
    const float* wv     = (const float*)d_in[6];
    const float* wo     = (const float*)d_in[7];
    const float* fnw    = (const float*)d_in[8];
    const float* rw     = (const float*)d_in[9];
    const float* w1     = (const float*)d_in[10];
    const float* w2     = (const float*)d_in[11];
    float* out = (float*)d_out;

    float *p_hn, *p_q, *p_k, *p_v, *p_o, *p_h, *p_fn;
    cudaGetSymbolAddress((void**)&p_hn, g_hn);
    cudaGetSymbolAddress((void**)&p_q,  g_q);
    cudaGetSymbolAddress((void**)&p_k,  g_k);
    cudaGetSymbolAddress((void**)&p_v,  g_v);
    cudaGetSymbolAddress((void**)&p_o,  g_o);
    cudaGetSymbolAddress((void**)&p_h,  g_h);
    cudaGetSymbolAddress((void**)&p_fn, g_fn);

    zero_kernel<<<1, 32>>>();

    // attention norm
    rmsnorm_kernel<<<ROWS, 256>>>(x, anw, p_hn, 1e-5f);

    // QKV projections
    sgemm_kernel<<<dim3(16, 64), 256>>>(p_hn, wq, nullptr, p_q, ROWS, HH*HDD, DD);
    sgemm_kernel<<<dim3(4, 64), 256>>>(p_hn, wk, nullptr, p_k, ROWS, HKK*HDD, DD);
    sgemm_kernel<<<dim3(4, 64), 256>>>(p_hn, wv, nullptr, p_v, ROWS, HKK*HDD, DD);

    // RoPE
    {
        int tq = ROWS * HH * 32;
        rope_kernel<<<(tq + 255) / 256, 256>>>(p_q, fcos, fsin, HH, tq);
        int tk = ROWS * HKK * 32;
        rope_kernel<<<(tk + 255) / 256, 256>>>(p_k, fcos, fsin, HKK, tk);
    }

    // attention
    attn_kernel<<<dim3(SS / 64, HH, BB), 256>>>(p_q, p_k, p_v, p_o);

    // output projection + residual
    sgemm_kernel<<<dim3(16, 64), 256>>>(p_o, wo, x, p_h, ROWS, DD, HH*HDD);

    // ffn norm
    rmsnorm_kernel<<<ROWS, 256>>>(p_h, fnw, p_fn, 1e-6f);

    // router + compaction
    router_kernel<<<ROWS, 128>>>(p_fn, rw);
    scan_kernel<<<1, 1>>>();
    scatter_kernel<<<NASSIGN / 256, 256>>>();

    // expert GEMMs
    moe_gemm1_kernel<<<dim3(DHH / 64, 64, EE), 256>>>(p_fn, w1);
    moe_gemm2_kernel<<<dim3(DD / 64, 64, EE), 256>>>(w2);

    // final residual sum
    final_add_kernel<<<(ROWS * DD + 255) / 256, 256>>>(out);

    (void)in_sizes; (void)n_in; (void)out_size;
}

// round 2
// speedup vs baseline: 2.8802x; 2.8802x over previous
#include <cuda_runtime.h>
#include <cuda_bf16.h>
#include <cstdint>

// Problem constants
#define BB 2
#define SS 2048
#define DD 1024
#define HH 16
#define HKK 4
#define HDD 64
#define WINN 1024
#define EE 8
#define DHH 2048
#define ROWS (BB*SS)          // 4096
#define NASSIGN (ROWS*2)      // 8192

// GEMM tile config
#define BM 128
#define BN 128
#define BKS 16
#define SA 136
#define SB 136

// ---------------- scratch (static device globals; no allocations) ----------------
__device__ float g_hn[ROWS*DD];
__device__ float g_q [ROWS*HH*HDD];
__device__ float g_k [ROWS*HKK*HDD];
__device__ float g_v [ROWS*HKK*HDD];
__device__ float g_o [ROWS*HH*HDD];
__device__ float g_h [ROWS*DD];
__device__ float g_fn[ROWS*DD];
__device__ float g_h1[NASSIGN*DHH];   // 64 MB
__device__ float g_r [NASSIGN*DD];    // 32 MB
__device__ int   g_counts[EE];
__device__ int   g_cursor[EE];
__device__ int   g_offsets[EE+1];
__device__ int   g_topi[NASSIGN];
__device__ float g_topg[NASSIGN];
__device__ int   g_arow[NASSIGN];
__device__ float g_agate[NASSIGN];
__device__ int   g_adst[NASSIGN];

// ---------------- helpers ----------------
__device__ __forceinline__ uint32_t f2tf(float f) {
    uint32_t r; asm("cvt.rna.tf32.f32 %0, %1;" : "=r"(r) : "f"(f)); return r;
}

__device__ __forceinline__ void mma_tf32(float* c, const uint32_t* a, uint32_t b0, uint32_t b1) {
    asm volatile("mma.sync.aligned.m16n8k8.row.col.f32.tf32.tf32.f32 "
        "{%0,%1,%2,%3}, {%4,%5,%6,%7}, {%8,%9}, {%0,%1,%2,%3};"
        : "+f"(c[0]), "+f"(c[1]), "+f"(c[2]), "+f"(c[3])
        : "r"(a[0]), "r"(a[1]), "r"(a[2]), "r"(a[3]), "r"(b0), "r"(b1));
}

// ---------------- small kernels ----------------
__global__ void zero_kernel() {
    int t = threadIdx.x;
    if (t < EE) { g_counts[t] = 0; g_cursor[t] = 0; }
}

__global__ void rmsnorm_kernel(const float* __restrict__ x, const float* __restrict__ w,
                               float* __restrict__ y, float eps) {
    int row = blockIdx.x;
    int tid = threadIdx.x;                 // 256
    const float* xr = x + (size_t)row * DD;
    float s = 0.f;
    for (int d = tid; d < DD; d += 256) { float v = xr[d]; s += v * v; }
    __shared__ float red[256];
    red[tid] = s; __syncthreads();
    for (int st = 128; st > 0; st >>= 1) {
        if (tid < st) red[tid] += red[tid + st];
        __syncthreads();
    }
    float rms = rsqrtf(red[0] / (float)DD + eps);
    float* yr = y + (size_t)row * DD;
    for (int d = tid; d < DD; d += 256) yr[d] = xr[d] * rms * w[d];
}

__global__ void rope_kernel(float* __restrict__ t, const float* __restrict__ fc,
                            const float* __restrict__ fs, int nh, int total) {
    int idx = blockIdx.x * blockDim.x + threadIdx.x;
    if (idx >= total) return;              // total = ROWS*nh*32
    int i = idx & 31;
    int h = (idx >> 5) % nh;
    int r = idx / (nh * 32);               // b*S + s
    int s = r & (SS - 1);
    float c  = fc[s * 32 + i];
    float sn = fs[s * 32 + i];
    size_t base = (size_t)r * (nh * HDD) + h * HDD + 2 * i;
    float t0 = t[base], t1 = t[base + 1];
    t[base]     = t0 * c - t1 * sn;
    t[base + 1] = t0 * sn + t1 * c;
}

// ---------------- tf32 tensor-core GEMM ----------------
// MODE 0: C[M,N] = A[M,K] @ B[K,N] (+X if non-null). grid (N/128, M/128)
// MODE 1: moe1: gather rows of A=fn via g_arow, B = w1[e], silu -> g_h1. grid (N/128, 64, E)
// MODE 2: moe2: A = g_h1 rows [off..off+cnt), B = w2[e], gate-scatter -> g_r. grid (N/128, 64, E)
template<int MODE>
__global__ __launch_bounds__(256, 2)
void tcgemm(const float* __restrict__ Ag, const float* __restrict__ Bg,
            const float* __restrict__ Xg, float* __restrict__ Cg,
            int M, int N, int K)
{
    __shared__ __align__(16) uint32_t As[2][BKS*SA];
    __shared__ __align__(16) uint32_t Bs[2][BKS*SB];
    __shared__ int   rows_s[BM];
    __shared__ int   adst_s[BM];
    __shared__ float agate_s[BM];

    const int tid  = threadIdx.x;
    const int rt0  = blockIdx.y * BM;
    const int col0 = blockIdx.x * BN;
    int cnt = M, off = 0;

    if (MODE >= 1) {
        const int e = blockIdx.z;
        cnt = g_counts[e];
        if (rt0 >= cnt) return;
        off = g_offsets[e];
        Bg += (size_t)e * (size_t)K * N;
    }
    if (MODE == 1) {
        if (tid < BM) {
            int r = rt0 + tid; if (r >= cnt) r = cnt - 1;
            rows_s[tid] = g_arow[off + r];
        }
        __syncthreads();
    }
    if (MODE == 2) {
        if (tid < BM) {
            int r = rt0 + tid; if (r >= cnt) r = cnt - 1;
            adst_s[tid]  = g_adst[off + r];
            agate_s[tid] = g_agate[off + r];
        }
    }

    // staging thread mapping
    const int ar0 = tid >> 2, ac4 = tid & 3;   // A: rows ar0, ar0+64 ; k cols 4*ac4..+3
    const int bk  = tid >> 4, bn4 = tid & 15;  // B: k-row bk ; n cols 4*bn4, 4*(bn4+16)

    // per-thread global row base pointers for the two staged A rows
    const float* arow_ptr[2];
    #pragma unroll
    for (int i = 0; i < 2; i++) {
        int r = ar0 + i * 64;
        size_t grow;
        if (MODE == 0)      grow = (size_t)(rt0 + r);
        else if (MODE == 1) grow = (size_t)rows_s[r];
        else { int rr = rt0 + r; if (rr >= cnt) rr = cnt - 1; grow = (size_t)(off + rr); }
        arow_ptr[i] = (MODE == 2 ? (const float*)g_h1 : Ag) + grow * (size_t)K;
    }
    const float* Brow = Bg + col0;

    float4 av[2], bv[2];
    // prologue: tile 0
    #pragma unroll
    for (int i = 0; i < 2; i++) av[i] = *(const float4*)(arow_ptr[i] + 4*ac4);
    #pragma unroll
    for (int i = 0; i < 2; i++) bv[i] = *(const float4*)(Brow + (size_t)bk * N + 4*(bn4 + 16*i));
    #pragma unroll
    for (int i = 0; i < 2; i++) {
        int m = ar0 + 64*i;
        As[0][(4*ac4+0)*SA + m] = f2tf(av[i].x);
        As[0][(4*ac4+1)*SA + m] = f2tf(av[i].y);
        As[0][(4*ac4+2)*SA + m] = f2tf(av[i].z);
        As[0][(4*ac4+3)*SA + m] = f2tf(av[i].w);
    }
    #pragma unroll
    for (int i = 0; i < 2; i++) {
        uint4 u = make_uint4(f2tf(bv[i].x), f2tf(bv[i].y), f2tf(bv[i].z), f2tf(bv[i].w));
        *(uint4*)&Bs[0][bk*SB + 4*(bn4 + 16*i)] = u;
    }
    __syncthreads();

    const int lane = tid & 31, warp = tid >> 5;
    const int wm = warp & 3, wn = warp >> 2;
    const int g = lane >> 2, cq = lane & 3;

    float acc[2][8][4];
    #pragma unroll
    for (int mi = 0; mi < 2; mi++)
        #pragma unroll
        for (int ni = 0; ni < 8; ni++)
            #pragma unroll
            for (int j = 0; j < 4; j++) acc[mi][ni][j] = 0.f;

    const int nk = K / BKS;
    for (int kt = 0; kt < nk; kt++) {
        const int cur = kt & 1;
        const bool pf = (kt + 1 < nk);
        if (pf) {
            const int k0 = (kt + 1) * BKS;
            #pragma unroll
            for (int i = 0; i < 2; i++) av[i] = *(const float4*)(arow_ptr[i] + k0 + 4*ac4);
            #pragma unroll
            for (int i = 0; i < 2; i++) bv[i] = *(const float4*)(Brow + (size_t)(k0 + bk) * N + 4*(bn4 + 16*i));
        }
        // compute on buffer `cur`
        #pragma unroll
        for (int ks = 0; ks < 2; ks++) {
            const int kb = ks * 8 + cq;
            uint32_t a[2][4];
            #pragma unroll
            for (int mi = 0; mi < 2; mi++) {
                const int m = wm*32 + mi*16 + g;
                a[mi][0] = As[cur][kb*SA + m];
                a[mi][1] = As[cur][kb*SA + m + 8];
                a[mi][2] = As[cur][(kb+4)*SA + m];
                a[mi][3] = As[cur][(kb+4)*SA + m + 8];
            }
            #pragma unroll
            for (int ni = 0; ni < 8; ni++) {
                const int n = wn*64 + ni*8 + g;
                uint32_t b0 = Bs[cur][kb*SB + n];
                uint32_t b1 = Bs[cur][(kb+4)*SB + n];
                mma_tf32(acc[0][ni], a[0], b0, b1);
                mma_tf32(acc[1][ni], a[1], b0, b1);
            }
        }
        if (pf) {
            const int nxt = cur ^ 1;
            #pragma unroll
            for (int i = 0; i < 2; i++) {
                int m = ar0 + 64*i;
                As[nxt][(4*ac4+0)*SA + m] = f2tf(av[i].x);
                As[nxt][(4*ac4+1)*SA + m] = f2tf(av[i].y);
                As[nxt][(4*ac4+2)*SA + m] = f2tf(av[i].z);
                As[nxt][(4*ac4+3)*SA + m] = f2tf(av[i].w);
            }
            #pragma unroll
            for (int i = 0; i < 2; i++) {
                uint4 u = make_uint4(f2tf(bv[i].x), f2tf(bv[i].y), f2tf(bv[i].z), f2tf(bv[i].w));
                *(uint4*)&Bs[nxt][bk*SB + 4*(bn4 + 16*i)] = u;
            }
        }
        __syncthreads();
    }

    // epilogue
    #pragma unroll
    for (int mi = 0; mi < 2; mi++) {
        #pragma unroll
        for (int rs = 0; rs < 2; rs++) {
            const int rr = wm*32 + mi*16 + g + rs*8;     // local row in 128-tile
            #pragma unroll
            for (int ni = 0; ni < 8; ni++) {
                const int cc = wn*64 + ni*8 + 2*cq;
                float v0 = acc[mi][ni][rs*2+0];
                float v1 = acc[mi][ni][rs*2+1];
                if (MODE == 0) {
                    size_t base = (size_t)(rt0 + rr) * N + col0 + cc;
                    if (Xg) { v0 += Xg[base]; v1 += Xg[base+1]; }
                    float2 o; o.x = v0; o.y = v1;
                    *(float2*)&Cg[base] = o;
                } else if (MODE == 1) {
                    const int r = rt0 + rr;
                    if (r < cnt) {
                        size_t base = (size_t)(off + r) * DHH + col0 + cc;
                        g_h1[base]   = v0 / (1.f + __expf(-v0));
                        g_h1[base+1] = v1 / (1.f + __expf(-v1));
                    }
                } else {
                    const int r = rt0 + rr;
                    if (r < cnt) {
                        const int dst = adst_s[rr];
                        const float gate = agate_s[rr];
                        size_t base = (size_t)dst * DD + col0 + cc;
                        g_r[base]   = gate * v0;
                        g_r[base+1] = gate * v1;
                    }
                }
            }
        }
    }
}

// ---------------- flash attention: 64-query x 32-key tiles ----------------
__global__ void attn_kernel(const float* __restrict__ q, const float* __restrict__ kmat,
                            const float* __restrict__ vmat, float* __restrict__ o) {
    const int qt = blockIdx.x, h = blockIdx.y, b = blockIdx.z;
    const int hk = h >> 2;
    const int q0 = qt * 64;
    __shared__ __align__(16) float Qs[64][68];
    __shared__ __align__(16) float Ks[64][36];
    __shared__ __align__(16) float Vs[32][68];
    __shared__ __align__(16) float Ps[64][36];
    __shared__ float m_s[64], l_s[64], al_s[64];
    const int tid = threadIdx.x;
    const int tx = tid & 15, ty = tid >> 4;

    #pragma unroll
    for (int i = 0; i < 16; i++) {
        int idx = tid + i * 256; int d = idx & 63, r = idx >> 6;
        Qs[d][r] = q[((size_t)(b * SS + q0 + r)) * (HH*HDD) + h * HDD + d];
    }
    if (tid < 64) { m_s[tid] = -1e30f; l_s[tid] = 0.f; }
    __syncthreads();

    float acc[4][4] = {};
    int jlo = q0 - (WINN - 1); if (jlo < 0) jlo = 0;
    const int jt0 = jlo >> 5, jt1 = (q0 + 63) >> 5;
    for (int jt = jt0; jt <= jt1; jt++) {
        const int j0 = jt << 5;
        #pragma unroll
        for (int i = 0; i < 8; i++) {
            int idx = tid + i * 256; int d = idx & 63, r = idx >> 6;
            Ks[d][r] = kmat[((size_t)(b * SS + j0 + r)) * (HKK*HDD) + hk * HDD + d];
        }
        __syncthreads();
        float s2[4][2] = {};
        #pragma unroll
        for (int d = 0; d < 64; d++) {
            float4 a  = *reinterpret_cast<const float4*>(&Qs[d][ty * 4]);
            float2 bq = *reinterpret_cast<const float2*>(&Ks[d][tx * 2]);
            s2[0][0] += a.x*bq.x; s2[0][1] += a.x*bq.y;
            s2[1][0] += a.y*bq.x; s2[1][1] += a.y*bq.y;
            s2[2][0] += a.z*bq.x; s2[2][1] += a.z*bq.y;
            s2[3][0] += a.w*bq.x; s2[3][1] += a.w*bq.y;
        }
        #pragma unroll
        for (int i2 = 0; i2 < 4; i2++)
            #pragma unroll
            for (int j2 = 0; j2 < 2; j2++) {
                int qi = q0 + ty * 4 + i2, kj = j0 + tx * 2 + j2;
                bool ok = (kj <= qi) && (qi - kj < WINN);
                Ps[ty*4+i2][tx*2+j2] = ok ? s2[i2][j2] * 0.125f : -1e30f;
            }
        __syncthreads();
        #pragma unroll
        for (int i = 0; i < 8; i++) {
            int idx = tid + i * 256; int d = idx & 63, r = idx >> 6;
            Vs[r][d] = vmat[((size_t)(b * SS + j0 + r)) * (HKK*HDD) + hk * HDD + d];
        }
        if (tid < 64) {
            float m_old = m_s[tid];
            float mx = m_old;
            #pragma unroll
            for (int c = 0; c < 32; c++) mx = fmaxf(mx, Ps[tid][c]);
            float alpha = __expf(m_old - mx);
            float lsum = 0.f;
            #pragma unroll
            for (int c = 0; c < 32; c++) {
                float s = Ps[tid][c];
                float p = (s < -1e29f) ? 0.f : __expf(s - mx);
                Ps[tid][c] = p; lsum += p;
            }
            l_s[tid] = l_s[tid] * alpha + lsum;
            m_s[tid] = mx; al_s[tid] = alpha;
        }
        __syncthreads();
        #pragma unroll
        for (int i2 = 0; i2 < 4; i2++) {
            float al = al_s[ty * 4 + i2];
            acc[i2][0]*=al; acc[i2][1]*=al; acc[i2][2]*=al; acc[i2][3]*=al;
        }
        #pragma unroll
        for (int c = 0; c < 32; c++) {
            float4 bv = *reinterpret_cast<const float4*>(&Vs[c][tx * 4]);
            #pragma unroll
            for (int i2 = 0; i2 < 4; i2++) {
                float p = Ps[ty*4+i2][c];
                acc[i2][0]+=p*bv.x; acc[i2][1]+=p*bv.y; acc[i2][2]+=p*bv.z; acc[i2][3]+=p*bv.w;
            }
        }
        __syncthreads();
    }
    #pragma unroll
    for (int i2 = 0; i2 < 4; i2++) {
        int qr = ty * 4 + i2;
        float inv = 1.f / l_s[qr];
        size_t base = ((size_t)(b * SS + q0 + qr)) * (HH*HDD) + h * HDD + tx * 4;
        o[base+0]=acc[i2][0]*inv; o[base+1]=acc[i2][1]*inv;
        o[base+2]=acc[i2][2]*inv; o[base+3]=acc[i2][3]*inv;
    }
}

// ---------------- router / MoE bookkeeping ----------------
__global__ void router_kernel(const float* __restrict__ fn, const float* __restrict__ rw) {
    const int row = blockIdx.x;
    const int tid = threadIdx.x;           // 128
    float l[EE] = {};
    for (int d = tid; d < DD; d += 128) {
        float x = fn[(size_t)row * DD + d];
        #pragma unroll
        for (int e = 0; e < EE; e++) l[e] += x * rw[d * EE + e];
    }
    __shared__ float part[EE][128];
    #pragma unroll
    for (int e = 0; e < EE; e++) part[e][tid] = l[e];
    __syncthreads();
    for (int st = 64; st > 0; st >>= 1) {
        if (tid < st) {
            #pragma unroll
            for (int e = 0; e < EE; e++) part[e][tid] += part[e][tid + st];
        }
        __syncthreads();
    }
    if (tid == 0) {
        float lg[EE];
        #pragma unroll
        for (int e = 0; e < EE; e++) lg[e] = part[e][0];
        int i1 = 0;
        #pragma unroll
        for (int e = 1; e < EE; e++) if (lg[e] > lg[i1]) i1 = e;
        int i2 = (i1 == 0) ? 1 : 0;
        #pragma unroll
        for (int e = 0; e < EE; e++) if (e != i1 && lg[e] > lg[i2]) i2 = e;
        float g1 = 1.f / (1.f + __expf(lg[i2] - lg[i1]));
        float g2 = 1.f - g1;
        g_topi[row*2]   = i1; g_topg[row*2]   = g1;
        g_topi[row*2+1] = i2; g_topg[row*2+1] = g2;
        atomicAdd(&g_counts[i1], 1);
        atomicAdd(&g_counts[i2], 1);
    }
}

__global__ void scan_kernel() {
    int s = 0;
    for (int e = 0; e < EE; e++) { g_offsets[e] = s; s += g_counts[e]; }
    g_offsets[EE] = s;
}

__global__ void scatter_kernel() {
    int idx = blockIdx.x * blockDim.x + threadIdx.x;
    if (idx >= NASSIGN) return;
    int e = g_topi[idx];
    int pos = atomicAdd(&g_cursor[e], 1);
    int a = g_offsets[e] + pos;
    g_arow[a]  = idx >> 1;
    g_agate[a] = g_topg[idx];
    g_adst[a]  = idx;
}

__global__ void final_add_kernel(float* __restrict__ out) {
    int idx = blockIdx.x * blockDim.x + threadIdx.x;
    if (idx >= ROWS * DD) return;
    int row = idx >> 10, col = idx & 1023;
    out[idx] = g_h[idx] + g_r[((size_t)row * 2) * DD + col]
                        + g_r[((size_t)row * 2 + 1) * DD + col];
}

// ---------------- launch ----------------
extern "C" void kernel_launch(void* const* d_in, const int* in_sizes, int n_in,
                              void* d_out, int out_size) {
    const float* x      = (const float*)d_in[0];
    const float* fcos   = (const float*)d_in[1];
    const float* fsin   = (const float*)d_in[2];
    const float* anw    = (const float*)d_in[3];
    const float* wq     = (const float*)d_in[4];
    const float* wk     = (const float*)d_in[5];
    const float* wv     = (const float*)d_in[6];
    const float* wo     = (const float*)d_in[7];
    const float* fnw    = (const float*)d_in[8];
    const float* rw     = (const float*)d_in[9];
    const float* w1     = (const float*)d_in[10];
    const float* w2     = (const float*)d_in[11];
    float* out = (float*)d_out;

    float *p_hn, *p_q, *p_k, *p_v, *p_o, *p_h, *p_fn;
    cudaGetSymbolAddress((void**)&p_hn, g_hn);
    cudaGetSymbolAddress((void**)&p_q,  g_q);
    cudaGetSymbolAddress((void**)&p_k,  g_k);
    cudaGetSymbolAddress((void**)&p_v,  g_v);
    cudaGetSymbolAddress((void**)&p_o,  g_o);
    cudaGetSymbolAddress((void**)&p_h,  g_h);
    cudaGetSymbolAddress((void**)&p_fn, g_fn);

    zero_kernel<<<1, 32>>>();

    // attention norm
    rmsnorm_kernel<<<ROWS, 256>>>(x, anw, p_hn, 1e-5f);

    // QKV projections (tf32 tensor core)
    tcgemm<0><<<dim3(8, 32), 256>>>(p_hn, wq, nullptr, p_q, ROWS, HH*HDD, DD);
    tcgemm<0><<<dim3(2, 32), 256>>>(p_hn, wk, nullptr, p_k, ROWS, HKK*HDD, DD);
    tcgemm<0><<<dim3(2, 32), 256>>>(p_hn, wv, nullptr, p_v, ROWS, HKK*HDD, DD);

    // RoPE
    {
        int tq = ROWS * HH * 32;
        rope_kernel<<<(tq + 255) / 256, 256>>>(p_q, fcos, fsin, HH, tq);
        int tk = ROWS * HKK * 32;
        rope_kernel<<<(tk + 255) / 256, 256>>>(p_k, fcos, fsin, HKK, tk);
    }

    // attention
    attn_kernel<<<dim3(SS / 64, HH, BB), 256>>>(p_q, p_k, p_v, p_o);

    // output projection + residual
    tcgemm<0><<<dim3(8, 32), 256>>>(p_o, wo, x, p_h, ROWS, DD, HH*HDD);

    // ffn norm
    rmsnorm_kernel<<<ROWS, 256>>>(p_h, fnw, p_fn, 1e-6f);

    // router + compaction
    router_kernel<<<ROWS, 128>>>(p_fn, rw);
    scan_kernel<<<1, 1>>>();
    scatter_kernel<<<NASSIGN / 256, 256>>>();

    // expert GEMMs (tf32 tensor core)
    tcgemm<1><<<dim3(DHH / BN, NASSIGN / BM, EE), 256>>>(p_fn, w1, nullptr, nullptr, 0, DHH, DD);
    tcgemm<2><<<dim3(DD / BN, NASSIGN / BM, EE), 256>>>(nullptr, w2, nullptr, nullptr, 0, DD, DHH);

    // final residual sum
    final_add_kernel<<<(ROWS * DD + 255) / 256, 256>>>(out);

    (void)in_sizes; (void)n_in; (void)out_size;
}

// round 3
// speedup vs baseline: 3.8549x; 1.3384x over previous
#include <cuda_runtime.h>
#include <cuda_bf16.h>
#include <cstdint>

// Problem constants
#define BB 2
#define SS 2048
#define DD 1024
#define HH 16
#define HKK 4
#define HDD 64
#define WINN 1024
#define EE 8
#define DHH 2048
#define ROWS (BB*SS)          // 4096
#define NASSIGN (ROWS*2)      // 8192

// GEMM tile config
#define BM 128
#define BN 128
#define BKS 16
#define SA 136
#define SB 136

// ---------------- scratch ----------------
__device__ float g_hn[ROWS*DD];
__device__ float g_q [ROWS*HH*HDD];
__device__ float g_k [ROWS*HKK*HDD];
__device__ float g_v [ROWS*HKK*HDD];
__device__ float g_o [ROWS*HH*HDD];
__device__ float g_h [ROWS*DD];
__device__ float g_fn[ROWS*DD];
__device__ float g_h1[NASSIGN*DHH];
__device__ float g_r [NASSIGN*DD];
__device__ int   g_counts[EE];
__device__ int   g_cursor[EE];
__device__ int   g_offsets[EE+1];
__device__ int   g_topi[NASSIGN];
__device__ float g_topg[NASSIGN];
__device__ int   g_arow[NASSIGN];
__device__ float g_agate[NASSIGN];
__device__ int   g_adst[NASSIGN];

// ---------------- helpers ----------------
__device__ __forceinline__ uint32_t f2tf(float f) {
    uint32_t r; asm("cvt.rna.tf32.f32 %0, %1;" : "=r"(r) : "f"(f)); return r;
}

__device__ __forceinline__ void mma_tf32(float* c, const uint32_t* a, uint32_t b0, uint32_t b1) {
    asm volatile("mma.sync.aligned.m16n8k8.row.col.f32.tf32.tf32.f32 "
        "{%0,%1,%2,%3}, {%4,%5,%6,%7}, {%8,%9}, {%0,%1,%2,%3};"
        : "+f"(c[0]), "+f"(c[1]), "+f"(c[2]), "+f"(c[3])
        : "r"(a[0]), "r"(a[1]), "r"(a[2]), "r"(a[3]), "r"(b0), "r"(b1));
}

// ---------------- small kernels ----------------
__global__ void zero_kernel() {
    int t = threadIdx.x;
    if (t < EE) { g_counts[t] = 0; g_cursor[t] = 0; }
}

__global__ void rmsnorm_kernel(const float* __restrict__ x, const float* __restrict__ w,
                               float* __restrict__ y, float eps) {
    int row = blockIdx.x;
    int tid = threadIdx.x;
    const float* xr = x + (size_t)row * DD;
    float s = 0.f;
    #pragma unroll
    for (int i = 0; i < 1; i++) {
        float4 v = *(const float4*)(xr + tid * 4);
        s = v.x*v.x + v.y*v.y + v.z*v.z + v.w*v.w;
    }
    __shared__ float red[256];
    red[tid] = s; __syncthreads();
    for (int st = 128; st > 0; st >>= 1) {
        if (tid < st) red[tid] += red[tid + st];
        __syncthreads();
    }
    float rms = rsqrtf(red[0] / (float)DD + eps);
    float4 v = *(const float4*)(xr + tid * 4);
    float4 wv = *(const float4*)(w + tid * 4);
    float4 ov;
    ov.x = v.x * rms * wv.x; ov.y = v.y * rms * wv.y;
    ov.z = v.z * rms * wv.z; ov.w = v.w * rms * wv.w;
    *(float4*)(y + (size_t)row * DD + tid * 4) = ov;
}

__global__ void rope_kernel(float* __restrict__ t, const float* __restrict__ fc,
                            const float* __restrict__ fs, int nh, int total) {
    int idx = blockIdx.x * blockDim.x + threadIdx.x;
    if (idx >= total) return;
    int i = idx & 31;
    int h = (idx >> 5) % nh;
    int r = idx / (nh * 32);
    int s = r & (SS - 1);
    float c  = fc[s * 32 + i];
    float sn = fs[s * 32 + i];
    size_t base = (size_t)r * (nh * HDD) + h * HDD + 2 * i;
    float t0 = t[base], t1 = t[base + 1];
    t[base]     = t0 * c - t1 * sn;
    t[base + 1] = t0 * sn + t1 * c;
}

// ---------------- tf32 tensor-core GEMM ----------------
// MODE 0: C = A@B (+X). grid (N/128, M/128)
// MODE 1: moe1 gather+silu -> g_h1
// MODE 2: moe2 gate-scatter -> g_r
// MODE 3: fused K/V proj: grid (4, 32); x<2 -> wk(Bg)->g_k ; else wv(Xg)->g_v. N=256.
template<int MODE>
__global__ __launch_bounds__(256, 2)
void tcgemm(const float* __restrict__ Ag, const float* __restrict__ Bg,
            const float* __restrict__ Xg, float* __restrict__ Cg,
            int M, int N, int K)
{
    __shared__ __align__(16) uint32_t As[2][BKS*SA];
    __shared__ __align__(16) uint32_t Bs[2][BKS*SB];
    __shared__ int   rows_s[BM];
    __shared__ int   adst_s[BM];
    __shared__ float agate_s[BM];

    const int tid  = threadIdx.x;
    const int rt0  = blockIdx.y * BM;
    int col0 = blockIdx.x * BN;
    int cnt = M, off = 0;
    const float* Bsel = Bg;
    float* Csel = Cg;

    if (MODE == 3) {
        const int sel = blockIdx.x >> 1;
        col0 = (blockIdx.x & 1) * BN;
        if (sel) { Bsel = Xg; Csel = g_v; } else { Csel = g_k; }
    }
    if (MODE == 1 || MODE == 2) {
        const int e = blockIdx.z;
        cnt = g_counts[e];
        if (rt0 >= cnt) return;
        off = g_offsets[e];
        Bsel = Bg + (size_t)e * (size_t)K * N;
    }
    if (MODE == 1) {
        if (tid < BM) {
            int r = rt0 + tid; if (r >= cnt) r = cnt - 1;
            rows_s[tid] = g_arow[off + r];
        }
        __syncthreads();
    }
    if (MODE == 2) {
        if (tid < BM) {
            int r = rt0 + tid; if (r >= cnt) r = cnt - 1;
            adst_s[tid]  = g_adst[off + r];
            agate_s[tid] = g_agate[off + r];
        }
    }

    const int ar0 = tid >> 2, ac4 = tid & 3;
    const int bk  = tid >> 4, bn4 = tid & 15;

    const float* arow_ptr[2];
    #pragma unroll
    for (int i = 0; i < 2; i++) {
        int r = ar0 + i * 64;
        size_t grow;
        if (MODE == 0 || MODE == 3) grow = (size_t)(rt0 + r);
        else if (MODE == 1) grow = (size_t)rows_s[r];
        else { int rr = rt0 + r; if (rr >= cnt) rr = cnt - 1; grow = (size_t)(off + rr); }
        arow_ptr[i] = (MODE == 2 ? (const float*)g_h1 : Ag) + grow * (size_t)K;
    }
    const float* Brow = Bsel + col0;

    float4 av[2], bv[2];
    #pragma unroll
    for (int i = 0; i < 2; i++) av[i] = *(const float4*)(arow_ptr[i] + 4*ac4);
    #pragma unroll
    for (int i = 0; i < 2; i++) bv[i] = *(const float4*)(Brow + (size_t)bk * N + 4*(bn4 + 16*i));
    #pragma unroll
    for (int i = 0; i < 2; i++) {
        int m = ar0 + 64*i;
        As[0][(4*ac4+0)*SA + m] = f2tf(av[i].x);
        As[0][(4*ac4+1)*SA + m] = f2tf(av[i].y);
        As[0][(4*ac4+2)*SA + m] = f2tf(av[i].z);
        As[0][(4*ac4+3)*SA + m] = f2tf(av[i].w);
    }
    #pragma unroll
    for (int i = 0; i < 2; i++) {
        uint4 u = make_uint4(f2tf(bv[i].x), f2tf(bv[i].y), f2tf(bv[i].z), f2tf(bv[i].w));
        *(uint4*)&Bs[0][bk*SB + 4*(bn4 + 16*i)] = u;
    }
    __syncthreads();

    const int lane = tid & 31, warp = tid >> 5;
    const int wm = warp & 3, wn = warp >> 2;
    const int g = lane >> 2, cq = lane & 3;

    float acc[2][8][4];
    #pragma unroll
    for (int mi = 0; mi < 2; mi++)
        #pragma unroll
        for (int ni = 0; ni < 8; ni++)
            #pragma unroll
            for (int j = 0; j < 4; j++) acc[mi][ni][j] = 0.f;

    const int nk = K / BKS;
    for (int kt = 0; kt < nk; kt++) {
        const int cur = kt & 1;
        const bool pf = (kt + 1 < nk);
        if (pf) {
            const int k0 = (kt + 1) * BKS;
            #pragma unroll
            for (int i = 0; i < 2; i++) av[i] = *(const float4*)(arow_ptr[i] + k0 + 4*ac4);
            #pragma unroll
            for (int i = 0; i < 2; i++) bv[i] = *(const float4*)(Brow + (size_t)(k0 + bk) * N + 4*(bn4 + 16*i));
        }
        #pragma unroll
        for (int ks = 0; ks < 2; ks++) {
            const int kb = ks * 8 + cq;
            uint32_t a[2][4];
            #pragma unroll
            for (int mi = 0; mi < 2; mi++) {
                const int m = wm*32 + mi*16 + g;
                a[mi][0] = As[cur][kb*SA + m];
                a[mi][1] = As[cur][kb*SA + m + 8];
                a[mi][2] = As[cur][(kb+4)*SA + m];
                a[mi][3] = As[cur][(kb+4)*SA + m + 8];
            }
            #pragma unroll
            for (int ni = 0; ni < 8; ni++) {
                const int n = wn*64 + ni*8 + g;
                uint32_t b0 = Bs[cur][kb*SB + n];
                uint32_t b1 = Bs[cur][(kb+4)*SB + n];
                mma_tf32(acc[0][ni], a[0], b0, b1);
                mma_tf32(acc[1][ni], a[1], b0, b1);
            }
        }
        if (pf) {
            const int nxt = cur ^ 1;
            #pragma unroll
            for (int i = 0; i < 2; i++) {
                int m = ar0 + 64*i;
                As[nxt][(4*ac4+0)*SA + m] = f2tf(av[i].x);
                As[nxt][(4*ac4+1)*SA + m] = f2tf(av[i].y);
                As[nxt][(4*ac4+2)*SA + m] = f2tf(av[i].z);
                As[nxt][(4*ac4+3)*SA + m] = f2tf(av[i].w);
            }
            #pragma unroll
            for (int i = 0; i < 2; i++) {
                uint4 u = make_uint4(f2tf(bv[i].x), f2tf(bv[i].y), f2tf(bv[i].z), f2tf(bv[i].w));
                *(uint4*)&Bs[nxt][bk*SB + 4*(bn4 + 16*i)] = u;
            }
        }
        __syncthreads();
    }

    #pragma unroll
    for (int mi = 0; mi < 2; mi++) {
        #pragma unroll
        for (int rs = 0; rs < 2; rs++) {
            const int rr = wm*32 + mi*16 + g + rs*8;
            #pragma unroll
            for (int ni = 0; ni < 8; ni++) {
                const int cc = wn*64 + ni*8 + 2*cq;
                float v0 = acc[mi][ni][rs*2+0];
                float v1 = acc[mi][ni][rs*2+1];
                if (MODE == 0 || MODE == 3) {
                    size_t base = (size_t)(rt0 + rr) * N + col0 + cc;
                    if (MODE == 0 && Xg) { v0 += Xg[base]; v1 += Xg[base+1]; }
                    float2 ov; ov.x = v0; ov.y = v1;
                    *(float2*)&Csel[base] = ov;
                } else if (MODE == 1) {
                    const int r = rt0 + rr;
                    if (r < cnt) {
                        size_t base = (size_t)(off + r) * DHH + col0 + cc;
                        g_h1[base]   = v0 / (1.f + __expf(-v0));
                        g_h1[base+1] = v1 / (1.f + __expf(-v1));
                    }
                } else {
                    const int r = rt0 + rr;
                    if (r < cnt) {
                        const int dst = adst_s[rr];
                        const float gate = agate_s[rr];
                        size_t base = (size_t)dst * DD + col0 + cc;
                        g_r[base]   = gate * v0;
                        g_r[base+1] = gate * v1;
                    }
                }
            }
        }
    }
}

// ---------------- tensor-core flash attention ----------------
// 128 queries/block, 8 warps x 16 rows. 64-key tiles. tf32 mma for QK^T and P@V.
#define KPAD 68
extern __shared__ uint32_t sm_attn[];
__global__ __launch_bounds__(256)
void attn_tc(const float* __restrict__ q, const float* __restrict__ k,
             const float* __restrict__ v, const float* __restrict__ o_unused) {
    uint32_t* Ks = sm_attn;                 // [key][d]  64*KPAD
    uint32_t* Vs = sm_attn + 64*KPAD;       // [d][key]  64*KPAD
    uint32_t* Ps = sm_attn + 2*64*KPAD;     // [qrow][key] 128*KPAD (also Q staging)
    const int qt = blockIdx.x, h = blockIdx.y, b = blockIdx.z, hk = h >> 2;
    const int q0 = qt * 128;
    const int tid = threadIdx.x, lane = tid & 31, w = tid >> 5;
    const int g = lane >> 2, cq = lane & 3;

    // stage Q -> Ps (tf32)
    {
        int row = tid >> 1, dh = (tid & 1) * 32;
        const float* src = q + ((size_t)(b * SS + q0 + row)) * (HH*HDD) + h * HDD + dh;
        #pragma unroll
        for (int i = 0; i < 8; i++) {
            float4 f = *(const float4*)(src + 4*i);
            uint32_t* dst = &Ps[row*KPAD + dh + 4*i];
            dst[0]=f2tf(f.x); dst[1]=f2tf(f.y); dst[2]=f2tf(f.z); dst[3]=f2tf(f.w);
        }
    }
    __syncthreads();
    uint32_t Qa[8][4];
    {
        const int r0 = w*16 + g;
        #pragma unroll
        for (int s = 0; s < 8; s++) {
            Qa[s][0] = Ps[r0*KPAD + 8*s + cq];
            Qa[s][1] = Ps[(r0+8)*KPAD + 8*s + cq];
            Qa[s][2] = Ps[r0*KPAD + 8*s + cq + 4];
            Qa[s][3] = Ps[(r0+8)*KPAD + 8*s + cq + 4];
        }
    }
    __syncthreads();

    float Oacc[8][4];
    #pragma unroll
    for (int nt = 0; nt < 8; nt++)
        #pragma unroll
        for (int j = 0; j < 4; j++) Oacc[nt][j] = 0.f;
    float m[2] = {-1e30f, -1e30f}, l[2] = {0.f, 0.f};

    int jlo = q0 - (WINN - 1); if (jlo < 0) jlo = 0;
    const int jt0 = jlo >> 6, jt1 = (q0 + 127) >> 6;
    const int qwmin = q0 + w*16, qwmax = qwmin + 15;

    for (int jt = jt0; jt <= jt1; jt++) {
        const int j0 = jt << 6;
        // stage K [key][d] and V transposed [d][key]
        {
            int key = tid >> 2, d0 = (tid & 3) * 16;
            const float* src = k + ((size_t)(b * SS + j0 + key)) * (HKK*HDD) + hk * HDD + d0;
            #pragma unroll
            for (int i = 0; i < 4; i++) {
                float4 f = *(const float4*)(src + 4*i);
                uint4 u = make_uint4(f2tf(f.x), f2tf(f.y), f2tf(f.z), f2tf(f.w));
                *(uint4*)&Ks[key*KPAD + d0 + 4*i] = u;
            }
            int vkey = tid & 63, vd0 = (tid >> 6) * 16;
            const float* vsrc = v + ((size_t)(b * SS + j0 + vkey)) * (HKK*HDD) + hk * HDD + vd0;
            #pragma unroll
            for (int i = 0; i < 4; i++) {
                float4 f = *(const float4*)(vsrc + 4*i);
                Vs[(vd0+4*i+0)*KPAD + vkey] = f2tf(f.x);
                Vs[(vd0+4*i+1)*KPAD + vkey] = f2tf(f.y);
                Vs[(vd0+4*i+2)*KPAD + vkey] = f2tf(f.z);
                Vs[(vd0+4*i+3)*KPAD + vkey] = f2tf(f.w);
            }
        }
        __syncthreads();
        // S = Q K^T
        float sacc[8][4];
        #pragma unroll
        for (int nt = 0; nt < 8; nt++)
            #pragma unroll
            for (int j = 0; j < 4; j++) sacc[nt][j] = 0.f;
        #pragma unroll
        for (int s = 0; s < 8; s++) {
            #pragma unroll
            for (int nt = 0; nt < 8; nt++) {
                uint32_t b0 = Ks[(nt*8+g)*KPAD + 8*s + cq];
                uint32_t b1 = Ks[(nt*8+g)*KPAD + 8*s + cq + 4];
                mma_tf32(sacc[nt], Qa[s], b0, b1);
            }
        }
        // scale + mask
        const bool need_mask = !((j0 + 63 <= qwmin) && (qwmax - j0 < WINN));
        #pragma unroll
        for (int nt = 0; nt < 8; nt++) {
            #pragma unroll
            for (int j = 0; j < 4; j++) {
                float sv = sacc[nt][j] * 0.125f;
                if (need_mask) {
                    int qi = qwmin + g + 8 * (j >> 1);
                    int kj = j0 + nt*8 + 2*cq + (j & 1);
                    if (!(kj <= qi && qi - kj < WINN)) sv = -1e30f;
                }
                sacc[nt][j] = sv;
            }
        }
        // online softmax per row-set
        #pragma unroll
        for (int rs = 0; rs < 2; rs++) {
            float mx = -1e30f;
            #pragma unroll
            for (int nt = 0; nt < 8; nt++)
                mx = fmaxf(mx, fmaxf(sacc[nt][2*rs], sacc[nt][2*rs+1]));
            mx = fmaxf(mx, __shfl_xor_sync(0xffffffffu, mx, 1));
            mx = fmaxf(mx, __shfl_xor_sync(0xffffffffu, mx, 2));
            float mnew = fmaxf(m[rs], mx);
            float alpha = __expf(m[rs] - mnew);
            float sum = 0.f;
            const int row = w*16 + g + 8*rs;
            #pragma unroll
            for (int nt = 0; nt < 8; nt++) {
                float p0 = sacc[nt][2*rs];
                float p1 = sacc[nt][2*rs+1];
                p0 = (p0 <= -1e29f) ? 0.f : __expf(p0 - mnew);
                p1 = (p1 <= -1e29f) ? 0.f : __expf(p1 - mnew);
                sum += p0 + p1;
                uint2 u; u.x = f2tf(p0); u.y = f2tf(p1);
                *(uint2*)&Ps[row*KPAD + nt*8 + 2*cq] = u;
            }
            sum += __shfl_xor_sync(0xffffffffu, sum, 1);
            sum += __shfl_xor_sync(0xffffffffu, sum, 2);
            l[rs] = l[rs] * alpha + sum;
            m[rs] = mnew;
            #pragma unroll
            for (int nt = 0; nt < 8; nt++) {
                Oacc[nt][2*rs]   *= alpha;
                Oacc[nt][2*rs+1] *= alpha;
            }
        }
        __syncwarp();
        // O += P V
        #pragma unroll
        for (int s = 0; s < 8; s++) {
            const int r0 = w*16 + g;
            uint32_t a[4];
            a[0] = Ps[r0*KPAD + 8*s + cq];
            a[1] = Ps[(r0+8)*KPAD + 8*s + cq];
            a[2] = Ps[r0*KPAD + 8*s + cq + 4];
            a[3] = Ps[(r0+8)*KPAD + 8*s + cq + 4];
            #pragma unroll
            for (int nt = 0; nt < 8; nt++) {
                uint32_t b0 = Vs[(nt*8+g)*KPAD + 8*s + cq];
                uint32_t b1 = Vs[(nt*8+g)*KPAD + 8*s + cq + 4];
                mma_tf32(Oacc[nt], a, b0, b1);
            }
        }
        __syncthreads();
    }
    // epilogue
    #pragma unroll
    for (int rs = 0; rs < 2; rs++) {
        const float inv = 1.f / l[rs];
        const int row = q0 + w*16 + g + 8*rs;
        #pragma unroll
        for (int nt = 0; nt < 8; nt++) {
            float2 ov;
            ov.x = Oacc[nt][2*rs]   * inv;
            ov.y = Oacc[nt][2*rs+1] * inv;
            *(float2*)&g_o[((size_t)(b * SS + row)) * (HH*HDD) + h * HDD + nt*8 + 2*cq] = ov;
        }
    }
}

// ---------------- router / MoE bookkeeping ----------------
__global__ void router_kernel(const float* __restrict__ fn, const float* __restrict__ rw) {
    const int row = blockIdx.x;
    const int tid = threadIdx.x;           // 128
    float l[EE] = {};
    for (int d = tid; d < DD; d += 128) {
        float x = fn[(size_t)row * DD + d];
        #pragma unroll
        for (int e = 0; e < EE; e++) l[e] += x * rw[d * EE + e];
    }
    __shared__ float part[EE][128];
    #pragma unroll
    for (int e = 0; e < EE; e++) part[e][tid] = l[e];
    __syncthreads();
    for (int st = 64; st > 0; st >>= 1) {
        if (tid < st) {
            #pragma unroll
            for (int e = 0; e < EE; e++) part[e][tid] += part[e][tid + st];
        }
        __syncthreads();
    }
    if (tid == 0) {
        float lg[EE];
        #pragma unroll
        for (int e = 0; e < EE; e++) lg[e] = part[e][0];
        int i1 = 0;
        #pragma unroll
        for (int e = 1; e < EE; e++) if (lg[e] > lg[i1]) i1 = e;
        int i2 = (i1 == 0) ? 1 : 0;
        #pragma unroll
        for (int e = 0; e < EE; e++) if (e != i1 && lg[e] > lg[i2]) i2 = e;
        float g1 = 1.f / (1.f + __expf(lg[i2] - lg[i1]));
        float g2 = 1.f - g1;
        g_topi[row*2]   = i1; g_topg[row*2]   = g1;
        g_topi[row*2+1] = i2; g_topg[row*2+1] = g2;
        atomicAdd(&g_counts[i1], 1);
        atomicAdd(&g_counts[i2], 1);
    }
}

__global__ void scan_kernel() {
    int s = 0;
    for (int e = 0; e < EE; e++) { g_offsets[e] = s; s += g_counts[e]; }
    g_offsets[EE] = s;
}

__global__ void scatter_kernel() {
    int idx = blockIdx.x * blockDim.x + threadIdx.x;
    if (idx >= NASSIGN) return;
    int e = g_topi[idx];
    int pos = atomicAdd(&g_cursor[e], 1);
    int a = g_offsets[e] + pos;
    g_arow[a]  = idx >> 1;
    g_agate[a] = g_topg[idx];
    g_adst[a]  = idx;
}

__global__ void final_add_kernel(float* __restrict__ out) {
    int idx = blockIdx.x * blockDim.x + threadIdx.x;
    if (idx >= ROWS * DD / 4) return;
    int row = idx >> 8, c4 = (idx & 255) * 4;
    float4 a = *(float4*)&g_h[(size_t)row * DD + c4];
    float4 r0 = *(float4*)&g_r[((size_t)row * 2) * DD + c4];
    float4 r1 = *(float4*)&g_r[((size_t)row * 2 + 1) * DD + c4];
    float4 ov;
    ov.x = a.x + r0.x + r1.x; ov.y = a.y + r0.y + r1.y;
    ov.z = a.z + r0.z + r1.z; ov.w = a.w + r0.w + r1.w;
    *(float4*)&((float*)out)[(size_t)row * DD + c4] = ov;
}

// ---------------- launch ----------------
extern "C" void kernel_launch(void* const* d_in, const int* in_sizes, int n_in,
                              void* d_out, int out_size) {
    const float* x      = (const float*)d_in[0];
    const float* fcos   = (const float*)d_in[1];
    const float* fsin   = (const float*)d_in[2];
    const float* anw    = (const float*)d_in[3];
    const float* wq     = (const float*)d_in[4];
    const float* wk     = (const float*)d_in[5];
    const float* wv     = (const float*)d_in[6];
    const float* wo     = (const float*)d_in[7];
    const float* fnw    = (const float*)d_in[8];
    const float* rw     = (const float*)d_in[9];
    const float* w1     = (const float*)d_in[10];
    const float* w2     = (const float*)d_in[11];
    float* out = (float*)d_out;

    float *p_hn, *p_q, *p_k, *p_v, *p_o, *p_h, *p_fn;
    cudaGetSymbolAddress((void**)&p_hn, g_hn);
    cudaGetSymbolAddress((void**)&p_q,  g_q);
    cudaGetSymbolAddress((void**)&p_k,  g_k);
    cudaGetSymbolAddress((void**)&p_v,  g_v);
    cudaGetSymbolAddress((void**)&p_o,  g_o);
    cudaGetSymbolAddress((void**)&p_h,  g_h);
    cudaGetSymbolAddress((void**)&p_fn, g_fn);

    static int attn_smem_set = 0;
    const int ATTN_SMEM = (64*KPAD + 64*KPAD + 128*KPAD) * 4;  // 69632 B
    if (!attn_smem_set) {
        cudaFuncSetAttribute(attn_tc, cudaFuncAttributeMaxDynamicSharedMemorySize, ATTN_SMEM);
        attn_smem_set = 1;
    }

    zero_kernel<<<1, 32>>>();

    rmsnorm_kernel<<<ROWS, 256>>>(x, anw, p_hn, 1e-5f);

    // QKV projections
    tcgemm<0><<<dim3(8, 32), 256>>>(p_hn, wq, nullptr, p_q, ROWS, HH*HDD, DD);
    tcgemm<3><<<dim3(4, 32), 256>>>(p_hn, wk, wv, nullptr, ROWS, HKK*HDD, DD);

    // RoPE
    {
        int tq = ROWS * HH * 32;
        rope_kernel<<<(tq + 255) / 256, 256>>>(p_q, fcos, fsin, HH, tq);
        int tk = ROWS * HKK * 32;
        rope_kernel<<<(tk + 255) / 256, 256>>>(p_k, fcos, fsin, HKK, tk);
    }

    // attention (tensor core)
    attn_tc<<<dim3(SS / 128, HH, BB), 256, ATTN_SMEM>>>(p_q, p_k, p_v, nullptr);

    // output projection + residual
    tcgemm<0><<<dim3(8, 32), 256>>>(p_o, wo, x, p_h, ROWS, DD, HH*HDD);

    rmsnorm_kernel<<<ROWS, 256>>>(p_h, fnw, p_fn, 1e-6f);

    // router + compaction
    router_kernel<<<ROWS, 128>>>(p_fn, rw);
    scan_kernel<<<1, 1>>>();
    scatter_kernel<<<NASSIGN / 256, 256>>>();

    // expert GEMMs
    tcgemm<1><<<dim3(DHH / BN, NASSIGN / BM, EE), 256>>>(p_fn, w1, nullptr, nullptr, 0, DHH, DD);
    tcgemm<2><<<dim3(DD / BN, NASSIGN / BM, EE), 256>>>(nullptr, w2, nullptr, nullptr, 0, DD, DHH);

    final_add_kernel<<<(ROWS * DD / 4 + 255) / 256, 256>>>(out);

    (void)in_sizes; (void)n_in; (void)out_size;
}

// round 4
// speedup vs baseline: 4.2778x; 1.1097x over previous
#include <cuda_runtime.h>
#include <cuda_bf16.h>
#include <cstdint>

// Problem constants
#define BB 2
#define SS 2048
#define DD 1024
#define HH 16
#define HKK 4
#define HDD 64
#define WINN 1024
#define EE 8
#define DHH 2048
#define ROWS (BB*SS)          // 4096
#define NASSIGN (ROWS*2)      // 8192

// GEMM tile config
#define BM 128
#define BN 128
#define BK 16
#define STAGES 4
#define SA 20                  // A smem row stride (floats): [m][k], 128x16
#define SBW 136                // B smem row stride (floats): [k][n], 16x128
#define ASZ (BM*SA)            // 2560 floats
#define BSZ (BK*SBW)           // 2176 floats
#define STAGE_F (ASZ+BSZ)      // 4736 floats per stage
#define GEMM_SMEM (STAGES*STAGE_F*4)   // 75776 bytes

// ---------------- scratch ----------------
__device__ __align__(16) float g_hn[ROWS*DD];
__device__ __align__(16) float g_q [ROWS*HH*HDD];
__device__ __align__(16) float g_k [ROWS*HKK*HDD];
__device__ __align__(16) float g_v [ROWS*HKK*HDD];
__device__ __align__(16) float g_o [ROWS*HH*HDD];
__device__ __align__(16) float g_h [ROWS*DD];
__device__ __align__(16) float g_fn[ROWS*DD];
__device__ __align__(16) float g_h1[NASSIGN*DHH];
__device__ __align__(16) float g_r [NASSIGN*DD];
__device__ int   g_counts[EE];
__device__ int   g_cursor[EE];
__device__ int   g_offsets[EE+1];
__device__ int   g_topi[NASSIGN];
__device__ float g_topg[NASSIGN];
__device__ int   g_arow[NASSIGN];
__device__ float g_agate[NASSIGN];
__device__ int   g_adst[NASSIGN];

// ---------------- helpers ----------------
__device__ __forceinline__ uint32_t f2tf(float f) {
    uint32_t r; asm("cvt.rna.tf32.f32 %0, %1;" : "=r"(r) : "f"(f)); return r;
}

__device__ __forceinline__ void mma_tf32(float* c, const uint32_t* a, uint32_t b0, uint32_t b1) {
    asm volatile("mma.sync.aligned.m16n8k8.row.col.f32.tf32.tf32.f32 "
        "{%0,%1,%2,%3}, {%4,%5,%6,%7}, {%8,%9}, {%0,%1,%2,%3};"
        : "+f"(c[0]), "+f"(c[1]), "+f"(c[2]), "+f"(c[3])
        : "r"(a[0]), "r"(a[1]), "r"(a[2]), "r"(a[3]), "r"(b0), "r"(b1));
}

__device__ __forceinline__ void cp16(float* smem_dst, const float* gsrc) {
    uint32_t s = (uint32_t)__cvta_generic_to_shared(smem_dst);
    asm volatile("cp.async.cg.shared.global [%0], [%1], 16;\n" :: "r"(s), "l"(gsrc));
}
__device__ __forceinline__ void cp_commit() { asm volatile("cp.async.commit_group;\n"); }
template<int N> __device__ __forceinline__ void cp_wait() {
    asm volatile("cp.async.wait_group %0;\n" :: "n"(N));
}

// ---------------- small kernels ----------------
__global__ void zero_kernel() {
    int t = threadIdx.x;
    if (t < EE) { g_counts[t] = 0; g_cursor[t] = 0; }
}

__global__ void rmsnorm_kernel(const float* __restrict__ x, const float* __restrict__ w,
                               float* __restrict__ y, float eps) {
    int row = blockIdx.x;
    int tid = threadIdx.x;
    const float* xr = x + (size_t)row * DD;
    float4 v = *(const float4*)(xr + tid * 4);
    float s = v.x*v.x + v.y*v.y + v.z*v.z + v.w*v.w;
    __shared__ float red[256];
    red[tid] = s; __syncthreads();
    for (int st = 128; st > 0; st >>= 1) {
        if (tid < st) red[tid] += red[tid + st];
        __syncthreads();
    }
    float rms = rsqrtf(red[0] / (float)DD + eps);
    float4 wv = *(const float4*)(w + tid * 4);
    float4 ov;
    ov.x = v.x * rms * wv.x; ov.y = v.y * rms * wv.y;
    ov.z = v.z * rms * wv.z; ov.w = v.w * rms * wv.w;
    *(float4*)(y + (size_t)row * DD + tid * 4) = ov;
}

// ---------------- tf32 tensor-core GEMM, cp.async 4-stage pipeline ----------------
// MODE 0: C = A@B (+X). grid (N/128, M/128). ROPE optionally applied (wq).
// MODE 1: moe1 gather+silu -> g_h1
// MODE 2: moe2 gate-scatter -> g_r
// MODE 3: fused K/V proj: grid (4, 32); blockIdx.x>>1: 0->wk(Bg)->g_k (ROPE), 1->wv(Xg)->g_v.
template<int MODE, bool ROPE>
__global__ __launch_bounds__(256, 2)
void tcgemm(const float* __restrict__ Ag, const float* __restrict__ Bg,
            const float* __restrict__ Xg, float* __restrict__ Cg,
            int M, int N, int K,
            const float* __restrict__ fcos, const float* __restrict__ fsin)
{
    extern __shared__ __align__(16) float sm[];
    __shared__ int   rows_s[BM];
    __shared__ int   adst_s[BM];
    __shared__ float agate_s[BM];

    const int tid  = threadIdx.x;
    const int rt0  = blockIdx.y * BM;
    int col0 = blockIdx.x * BN;
    int cnt = M, off = 0;
    const float* Bsel = Bg;
    float* Csel = Cg;
    int sel = 0;

    if (MODE == 3) {
        sel = blockIdx.x >> 1;
        col0 = (blockIdx.x & 1) * BN;
        if (sel) { Bsel = Xg; Csel = g_v; } else { Csel = g_k; }
    }
    if (MODE == 1 || MODE == 2) {
        const int e = blockIdx.z;
        cnt = g_counts[e];
        if (rt0 >= cnt) return;
        off = g_offsets[e];
        Bsel = Bg + (size_t)e * (size_t)K * N;
    }
    if (MODE == 1) {
        if (tid < BM) {
            int r = rt0 + tid; if (r >= cnt) r = cnt - 1;
            rows_s[tid] = g_arow[off + r];
        }
        __syncthreads();
    }
    if (MODE == 2) {
        if (tid < BM) {
            int r = rt0 + tid; if (r >= cnt) r = cnt - 1;
            adst_s[tid]  = g_adst[off + r];
            agate_s[tid] = g_agate[off + r];
        }
    }

    // staging mapping
    const int am0 = tid >> 2;                  // A rows am0, am0+64
    const int kc4 = (tid & 3) * 4;             // A 16B chunk column
    const int bkr = tid >> 5;                  // B k-rows bkr, bkr+8
    const int bnc = (tid & 31) * 4;            // B 16B chunk column

    const float* arow_ptr[2];
    #pragma unroll
    for (int i = 0; i < 2; i++) {
        int r = am0 + i * 64;
        size_t grow;
        if (MODE == 0 || MODE == 3) grow = (size_t)(rt0 + r);
        else if (MODE == 1) grow = (size_t)rows_s[r];
        else { int rr = rt0 + r; if (rr >= cnt) rr = cnt - 1; grow = (size_t)(off + rr); }
        arow_ptr[i] = (MODE == 2 ? (const float*)g_h1 : Ag) + grow * (size_t)K;
    }
    const float* Brow = Bsel + col0;

    const int nk = K / BK;

    // prologue: stages 0..STAGES-2
    #pragma unroll
    for (int s = 0; s < STAGES - 1; s++) {
        if (s < nk) {
            float* base = sm + s * STAGE_F;
            const int k0 = s * BK;
            cp16(base + am0*SA + kc4,        arow_ptr[0] + k0 + kc4);
            cp16(base + (64+am0)*SA + kc4,   arow_ptr[1] + k0 + kc4);
            float* bb = base + ASZ;
            cp16(bb + bkr*SBW + bnc,         Brow + (size_t)(k0 + bkr) * N + bnc);
            cp16(bb + (8+bkr)*SBW + bnc,     Brow + (size_t)(k0 + 8 + bkr) * N + bnc);
        }
        cp_commit();
    }

    const int lane = tid & 31, warp = tid >> 5;
    const int wm = warp & 3, wn = warp >> 2;
    const int g = lane >> 2, cq = lane & 3;

    float acc[2][8][4];
    #pragma unroll
    for (int mi = 0; mi < 2; mi++)
        #pragma unroll
        for (int ni = 0; ni < 8; ni++)
            #pragma unroll
            for (int j = 0; j < 4; j++) acc[mi][ni][j] = 0.f;

    for (int kt = 0; kt < nk; kt++) {
        cp_wait<STAGES-2>();
        __syncthreads();
        // issue stage kt+STAGES-1 (into buffer consumed at iter kt-1)
        {
            const int pf = kt + STAGES - 1;
            if (pf < nk) {
                float* base = sm + (pf % STAGES) * STAGE_F;
                const int k0 = pf * BK;
                cp16(base + am0*SA + kc4,        arow_ptr[0] + k0 + kc4);
                cp16(base + (64+am0)*SA + kc4,   arow_ptr[1] + k0 + kc4);
                float* bb = base + ASZ;
                cp16(bb + bkr*SBW + bnc,         Brow + (size_t)(k0 + bkr) * N + bnc);
                cp16(bb + (8+bkr)*SBW + bnc,     Brow + (size_t)(k0 + 8 + bkr) * N + bnc);
            }
            cp_commit();
        }
        const uint32_t* Au = (const uint32_t*)(sm + (kt % STAGES) * STAGE_F);
        const uint32_t* Bu = Au + ASZ;
        #pragma unroll
        for (int ks = 0; ks < 2; ks++) {
            const int kb = ks * 8 + cq;
            uint32_t a[2][4];
            #pragma unroll
            for (int mi = 0; mi < 2; mi++) {
                const int m = wm*32 + mi*16 + g;
                a[mi][0] = Au[m*SA + kb];
                a[mi][1] = Au[(m+8)*SA + kb];
                a[mi][2] = Au[m*SA + kb + 4];
                a[mi][3] = Au[(m+8)*SA + kb + 4];
            }
            #pragma unroll
            for (int ni = 0; ni < 8; ni++) {
                const int n = wn*64 + ni*8 + g;
                uint32_t b0 = Bu[kb*SBW + n];
                uint32_t b1 = Bu[(kb+4)*SBW + n];
                mma_tf32(acc[0][ni], a[0], b0, b1);
                mma_tf32(acc[1][ni], a[1], b0, b1);
            }
        }
    }

    // epilogue
    #pragma unroll
    for (int mi = 0; mi < 2; mi++) {
        #pragma unroll
        for (int rs = 0; rs < 2; rs++) {
            const int rr = wm*32 + mi*16 + g + rs*8;
            const int grow = rt0 + rr;
            float cth = 0.f, sth = 0.f;
            #pragma unroll
            for (int ni = 0; ni < 8; ni++) {
                const int cc = wn*64 + ni*8 + 2*cq;
                float v0 = acc[mi][ni][rs*2+0];
                float v1 = acc[mi][ni][rs*2+1];
                if (MODE == 0 || MODE == 3) {
                    const int NN = (MODE == 3) ? 256 : N;
                    size_t base = (size_t)grow * NN + col0 + cc;
                    if (ROPE && (MODE == 0 || sel == 0)) {
                        const int s = grow & (SS - 1);
                        const int i = ((col0 + cc) & 63) >> 1;
                        cth = fcos[s*32 + i]; sth = fsin[s*32 + i];
                        float o0 = v0 * cth - v1 * sth;
                        float o1 = v0 * sth + v1 * cth;
                        v0 = o0; v1 = o1;
                    }
                    if (MODE == 0 && Xg) { v0 += Xg[base]; v1 += Xg[base+1]; }
                    float2 ov; ov.x = v0; ov.y = v1;
                    *(float2*)&Csel[base] = ov;
                } else if (MODE == 1) {
                    if (rr < cnt - rt0 + 0 && (rt0 + rr) < cnt) {
                        size_t base = (size_t)(off + rt0 + rr) * DHH + col0 + cc;
                        g_h1[base]   = v0 / (1.f + __expf(-v0));
                        g_h1[base+1] = v1 / (1.f + __expf(-v1));
                    }
                } else {
                    if ((rt0 + rr) < cnt) {
                        const int dst = adst_s[rr];
                        const float gate = agate_s[rr];
                        size_t base = (size_t)dst * DD + col0 + cc;
                        g_r[base]   = gate * v0;
                        g_r[base+1] = gate * v1;
                    }
                }
            }
        }
    }
}

// ---------------- tensor-core flash attention ----------------
#define KPAD 68
extern __shared__ uint32_t sm_attn[];
__global__ __launch_bounds__(256)
void attn_tc(const float* __restrict__ q, const float* __restrict__ k,
             const float* __restrict__ v) {
    uint32_t* Ks = sm_attn;
    uint32_t* Vs = sm_attn + 64*KPAD;
    uint32_t* Ps = sm_attn + 2*64*KPAD;
    const int qt = blockIdx.x, h = blockIdx.y, b = blockIdx.z, hk = h >> 2;
    const int q0 = qt * 128;
    const int tid = threadIdx.x, lane = tid & 31, w = tid >> 5;
    const int g = lane >> 2, cq = lane & 3;

    {
        int row = tid >> 1, dh = (tid & 1) * 32;
        const float* src = q + ((size_t)(b * SS + q0 + row)) * (HH*HDD) + h * HDD + dh;
        #pragma unroll
        for (int i = 0; i < 8; i++) {
            float4 f = *(const float4*)(src + 4*i);
            uint32_t* dst = &Ps[row*KPAD + dh + 4*i];
            dst[0]=f2tf(f.x); dst[1]=f2tf(f.y); dst[2]=f2tf(f.z); dst[3]=f2tf(f.w);
        }
    }
    __syncthreads();
    uint32_t Qa[8][4];
    {
        const int r0 = w*16 + g;
        #pragma unroll
        for (int s = 0; s < 8; s++) {
            Qa[s][0] = Ps[r0*KPAD + 8*s + cq];
            Qa[s][1] = Ps[(r0+8)*KPAD + 8*s + cq];
            Qa[s][2] = Ps[r0*KPAD + 8*s + cq + 4];
            Qa[s][3] = Ps[(r0+8)*KPAD + 8*s + cq + 4];
        }
    }
    __syncthreads();

    float Oacc[8][4];
    #pragma unroll
    for (int nt = 0; nt < 8; nt++)
        #pragma unroll
        for (int j = 0; j < 4; j++) Oacc[nt][j] = 0.f;
    float m[2] = {-1e30f, -1e30f}, l[2] = {0.f, 0.f};

    int jlo = q0 - (WINN - 1); if (jlo < 0) jlo = 0;
    const int jt0 = jlo >> 6, jt1 = (q0 + 127) >> 6;
    const int qwmin = q0 + w*16, qwmax = qwmin + 15;

    for (int jt = jt0; jt <= jt1; jt++) {
        const int j0 = jt << 6;
        {
            int key = tid >> 2, d0 = (tid & 3) * 16;
            const float* src = k + ((size_t)(b * SS + j0 + key)) * (HKK*HDD) + hk * HDD + d0;
            #pragma unroll
            for (int i = 0; i < 4; i++) {
                float4 f = *(const float4*)(src + 4*i);
                uint4 u = make_uint4(f2tf(f.x), f2tf(f.y), f2tf(f.z), f2tf(f.w));
                *(uint4*)&Ks[key*KPAD + d0 + 4*i] = u;
            }
            int vkey = tid & 63, vd0 = (tid >> 6) * 16;
            const float* vsrc = v + ((size_t)(b * SS + j0 + vkey)) * (HKK*HDD) + hk * HDD + vd0;
            #pragma unroll
            for (int i = 0; i < 4; i++) {
                float4 f = *(const float4*)(vsrc + 4*i);
                Vs[(vd0+4*i+0)*KPAD + vkey] = f2tf(f.x);
                Vs[(vd0+4*i+1)*KPAD + vkey] = f2tf(f.y);
                Vs[(vd0+4*i+2)*KPAD + vkey] = f2tf(f.z);
                Vs[(vd0+4*i+3)*KPAD + vkey] = f2tf(f.w);
            }
        }
        __syncthreads();
        float sacc[8][4];
        #pragma unroll
        for (int nt = 0; nt < 8; nt++)
            #pragma unroll
            for (int j = 0; j < 4; j++) sacc[nt][j] = 0.f;
        #pragma unroll
        for (int s = 0; s < 8; s++) {
            #pragma unroll
            for (int nt = 0; nt < 8; nt++) {
                uint32_t b0 = Ks[(nt*8+g)*KPAD + 8*s + cq];
                uint32_t b1 = Ks[(nt*8+g)*KPAD + 8*s + cq + 4];
                mma_tf32(sacc[nt], Qa[s], b0, b1);
            }
        }
        const bool need_mask = !((j0 + 63 <= qwmin) && (qwmax - j0 < WINN));
        #pragma unroll
        for (int nt = 0; nt < 8; nt++) {
            #pragma unroll
            for (int j = 0; j < 4; j++) {
                float sv = sacc[nt][j] * 0.125f;
                if (need_mask) {
                    int qi = qwmin + g + 8 * (j >> 1);
                    int kj = j0 + nt*8 + 2*cq + (j & 1);
                    if (!(kj <= qi && qi - kj < WINN)) sv = -1e30f;
                }
                sacc[nt][j] = sv;
            }
        }
        #pragma unroll
        for (int rs = 0; rs < 2; rs++) {
            float mx = -1e30f;
            #pragma unroll
            for (int nt = 0; nt < 8; nt++)
                mx = fmaxf(mx, fmaxf(sacc[nt][2*rs], sacc[nt][2*rs+1]));
            mx = fmaxf(mx, __shfl_xor_sync(0xffffffffu, mx, 1));
            mx = fmaxf(mx, __shfl_xor_sync(0xffffffffu, mx, 2));
            float mnew = fmaxf(m[rs], mx);
            float alpha = __expf(m[rs] - mnew);
            float sum = 0.f;
            const int row = w*16 + g + 8*rs;
            #pragma unroll
            for (int nt = 0; nt < 8; nt++) {
                float p0 = sacc[nt][2*rs];
                float p1 = sacc[nt][2*rs+1];
                p0 = (p0 <= -1e29f) ? 0.f : __expf(p0 - mnew);
                p1 = (p1 <= -1e29f) ? 0.f : __expf(p1 - mnew);
                sum += p0 + p1;
                uint2 u; u.x = f2tf(p0); u.y = f2tf(p1);
                *(uint2*)&Ps[row*KPAD + nt*8 + 2*cq] = u;
            }
            sum += __shfl_xor_sync(0xffffffffu, sum, 1);
            sum += __shfl_xor_sync(0xffffffffu, sum, 2);
            l[rs] = l[rs] * alpha + sum;
            m[rs] = mnew;
            #pragma unroll
            for (int nt = 0; nt < 8; nt++) {
                Oacc[nt][2*rs]   *= alpha;
                Oacc[nt][2*rs+1] *= alpha;
            }
        }
        __syncwarp();
        #pragma unroll
        for (int s = 0; s < 8; s++) {
            const int r0 = w*16 + g;
            uint32_t a[4];
            a[0] = Ps[r0*KPAD + 8*s + cq];
            a[1] = Ps[(r0+8)*KPAD + 8*s + cq];
            a[2] = Ps[r0*KPAD + 8*s + cq + 4];
            a[3] = Ps[(r0+8)*KPAD + 8*s + cq + 4];
            #pragma unroll
            for (int nt = 0; nt < 8; nt++) {
                uint32_t b0 = Vs[(nt*8+g)*KPAD + 8*s + cq];
                uint32_t b1 = Vs[(nt*8+g)*KPAD + 8*s + cq + 4];
                mma_tf32(Oacc[nt], a, b0, b1);
            }
        }
        __syncthreads();
    }
    #pragma unroll
    for (int rs = 0; rs < 2; rs++) {
        const float inv = 1.f / l[rs];
        const int row = q0 + w*16 + g + 8*rs;
        #pragma unroll
        for (int nt = 0; nt < 8; nt++) {
            float2 ov;
            ov.x = Oacc[nt][2*rs]   * inv;
            ov.y = Oacc[nt][2*rs+1] * inv;
            *(float2*)&g_o[((size_t)(b * SS + row)) * (HH*HDD) + h * HDD + nt*8 + 2*cq] = ov;
        }
    }
}

// ---------------- router / MoE bookkeeping ----------------
__global__ void router_kernel(const float* __restrict__ fn, const float* __restrict__ rw) {
    const int row = blockIdx.x;
    const int tid = threadIdx.x;           // 128
    float l[EE] = {};
    for (int d = tid; d < DD; d += 128) {
        float x = fn[(size_t)row * DD + d];
        #pragma unroll
        for (int e = 0; e < EE; e++) l[e] += x * rw[d * EE + e];
    }
    __shared__ float part[EE][128];
    #pragma unroll
    for (int e = 0; e < EE; e++) part[e][tid] = l[e];
    __syncthreads();
    for (int st = 64; st > 0; st >>= 1) {
        if (tid < st) {
            #pragma unroll
            for (int e = 0; e < EE; e++) part[e][tid] += part[e][tid + st];
        }
        __syncthreads();
    }
    if (tid == 0) {
        float lg[EE];
        #pragma unroll
        for (int e = 0; e < EE; e++) lg[e] = part[e][0];
        int i1 = 0;
        #pragma unroll
        for (int e = 1; e < EE; e++) if (lg[e] > lg[i1]) i1 = e;
        int i2 = (i1 == 0) ? 1 : 0;
        #pragma unroll
        for (int e = 0; e < EE; e++) if (e != i1 && lg[e] > lg[i2]) i2 = e;
        float g1 = 1.f / (1.f + __expf(lg[i2] - lg[i1]));
        float g2 = 1.f - g1;
        g_topi[row*2]   = i1; g_topg[row*2]   = g1;
        g_topi[row*2+1] = i2; g_topg[row*2+1] = g2;
        atomicAdd(&g_counts[i1], 1);
        atomicAdd(&g_counts[i2], 1);
    }
}

__global__ void scan_kernel() {
    int s = 0;
    for (int e = 0; e < EE; e++) { g_offsets[e] = s; s += g_counts[e]; }
    g_offsets[EE] = s;
}

__global__ void scatter_kernel() {
    int idx = blockIdx.x * blockDim.x + threadIdx.x;
    if (idx >= NASSIGN) return;
    int e = g_topi[idx];
    int pos = atomicAdd(&g_cursor[e], 1);
    int a = g_offsets[e] + pos;
    g_arow[a]  = idx >> 1;
    g_agate[a] = g_topg[idx];
    g_adst[a]  = idx;
}

__global__ void final_add_kernel(float* __restrict__ out) {
    int idx = blockIdx.x * blockDim.x + threadIdx.x;
    if (idx >= ROWS * DD / 4) return;
    int row = idx >> 8, c4 = (idx & 255) * 4;
    float4 a = *(float4*)&g_h[(size_t)row * DD + c4];
    float4 r0 = *(float4*)&g_r[((size_t)row * 2) * DD + c4];
    float4 r1 = *(float4*)&g_r[((size_t)row * 2 + 1) * DD + c4];
    float4 ov;
    ov.x = a.x + r0.x + r1.x; ov.y = a.y + r0.y + r1.y;
    ov.z = a.z + r0.z + r1.z; ov.w = a.w + r0.w + r1.w;
    *(float4*)&out[(size_t)row * DD + c4] = ov;
}

// ---------------- launch ----------------
extern "C" void kernel_launch(void* const* d_in, const int* in_sizes, int n_in,
                              void* d_out, int out_size) {
    const float* x      = (const float*)d_in[0];
    const float* fcos   = (const float*)d_in[1];
    const float* fsin   = (const float*)d_in[2];
    const float* anw    = (const float*)d_in[3];
    const float* wq     = (const float*)d_in[4];
    const float* wk     = (const float*)d_in[5];
    const float* wv     = (const float*)d_in[6];
    const float* wo     = (const float*)d_in[7];
    const float* fnw    = (const float*)d_in[8];
    const float* rw     = (const float*)d_in[9];
    const float* w1     = (const float*)d_in[10];
    const float* w2     = (const float*)d_in[11];
    float* out = (float*)d_out;

    float *p_hn, *p_q, *p_k, *p_v, *p_o, *p_h, *p_fn;
    cudaGetSymbolAddress((void**)&p_hn, g_hn);
    cudaGetSymbolAddress((void**)&p_q,  g_q);
    cudaGetSymbolAddress((void**)&p_k,  g_k);
    cudaGetSymbolAddress((void**)&p_v,  g_v);
    cudaGetSymbolAddress((void**)&p_o,  g_o);
    cudaGetSymbolAddress((void**)&p_h,  g_h);
    cudaGetSymbolAddress((void**)&p_fn, g_fn);

    static int attrs_set = 0;
    const int ATTN_SMEM = (64*KPAD + 64*KPAD + 128*KPAD) * 4;  // 69632 B
    if (!attrs_set) {
        cudaFuncSetAttribute(attn_tc, cudaFuncAttributeMaxDynamicSharedMemorySize, ATTN_SMEM);
        cudaFuncSetAttribute(tcgemm<0,true>,  cudaFuncAttributeMaxDynamicSharedMemorySize, GEMM_SMEM);
        cudaFuncSetAttribute(tcgemm<0,false>, cudaFuncAttributeMaxDynamicSharedMemorySize, GEMM_SMEM);
        cudaFuncSetAttribute(tcgemm<3,true>,  cudaFuncAttributeMaxDynamicSharedMemorySize, GEMM_SMEM);
        cudaFuncSetAttribute(tcgemm<1,false>, cudaFuncAttributeMaxDynamicSharedMemorySize, GEMM_SMEM);
        cudaFuncSetAttribute(tcgemm<2,false>, cudaFuncAttributeMaxDynamicSharedMemorySize, GEMM_SMEM);
        attrs_set = 1;
    }

    zero_kernel<<<1, 32>>>();

    rmsnorm_kernel<<<ROWS, 256>>>(x, anw, p_hn, 1e-5f);

    // QKV projections with fused RoPE
    tcgemm<0,true><<<dim3(8, 32), 256, GEMM_SMEM>>>(p_hn, wq, nullptr, p_q, ROWS, HH*HDD, DD, fcos, fsin);
    tcgemm<3,true><<<dim3(4, 32), 256, GEMM_SMEM>>>(p_hn, wk, wv, nullptr, ROWS, HKK*HDD, DD, fcos, fsin);

    // attention (tensor core)
    attn_tc<<<dim3(SS / 128, HH, BB), 256, ATTN_SMEM>>>(p_q, p_k, p_v);

    // output projection + residual
    tcgemm<0,false><<<dim3(8, 32), 256, GEMM_SMEM>>>(p_o, wo, x, p_h, ROWS, DD, HH*HDD, nullptr, nullptr);

    rmsnorm_kernel<<<ROWS, 256>>>(p_h, fnw, p_fn, 1e-6f);

    // router + compaction
    router_kernel<<<ROWS, 128>>>(p_fn, rw);
    scan_kernel<<<1, 1>>>();
    scatter_kernel<<<NASSIGN / 256, 256>>>();

    // expert GEMMs
    tcgemm<1,false><<<dim3(DHH / BN, NASSIGN / BM, EE), 256, GEMM_SMEM>>>(p_fn, w1, nullptr, nullptr, 0, DHH, DD, nullptr, nullptr);
    tcgemm<2,false><<<dim3(DD / BN, NASSIGN / BM, EE), 256, GEMM_SMEM>>>(nullptr, w2, nullptr, nullptr, 0, DD, DHH, nullptr, nullptr);

    final_add_kernel<<<(ROWS * DD / 4 + 255) / 256, 256>>>(out);

    (void)in_sizes; (void)n_in; (void)out_size;
}